// round 9
// baseline (speedup 1.0000x reference)
#include <cuda_runtime.h>
#include <cuda_bf16.h>
#include <math.h>
#include <stdint.h>

// ---------------- problem constants (fixed shapes) ----------------
#define BATCH 8
#define C     64
#define HH    64
#define WW    64
#define HW    4096          // 64*64
#define HEADS 4
#define DK    32
#define HD    128           // HEADS*DK
#define KHW   1024          // 32*32 (stride-2 output)
#define THETA 0.5f
#define EPS_LN 1e-5f
#define NTOT  (BATCH*C*HW)  // 2097152
#define QK_SCALE 0.17677669529663687f  // 1/sqrt(32)

typedef unsigned long long ull;

// packed fp32x2 helpers
__device__ __forceinline__ void fma2(ull& d, ull a, ull b, ull c) {
    asm("fma.rn.f32x2 %0, %1, %2, %3;" : "=l"(d) : "l"(a), "l"(b), "l"(c));
}
__device__ __forceinline__ ull pack2(float lo, float hi) {
    ull r; asm("mov.b64 %0, {%1, %2};" : "=l"(r) : "f"(lo), "f"(hi)); return r;
}
__device__ __forceinline__ void unpack2(float& lo, float& hi, ull v) {
    asm("mov.b64 {%0, %1}, %2;" : "=f"(lo), "=f"(hi) : "l"(v));
}
__device__ __forceinline__ uint32_t bf16x2_of(float a, float b) {
    uint32_t r;
    asm("cvt.rn.satfinite.bf16x2.f32 %0, %1, %2;" : "=r"(r) : "f"(b), "f"(a));
    return r;   // lo=a, hi=b
}

// warp mma: D(16x8,f32) += A(16x16,bf16,row) * B(16x8,bf16,col)
__device__ __forceinline__ void mma_bf16(float* d, const uint32_t* a,
                                         uint32_t b0, uint32_t b1) {
    asm volatile("mma.sync.aligned.m16n8k16.row.col.f32.bf16.bf16.f32 "
        "{%0,%1,%2,%3}, {%4,%5,%6,%7}, {%8,%9}, {%0,%1,%2,%3};"
        : "+f"(d[0]), "+f"(d[1]), "+f"(d[2]), "+f"(d[3])
        : "r"(a[0]), "r"(a[1]), "r"(a[2]), "r"(a[3]), "r"(b0), "r"(b1));
}

// cp.async 16B (LDGSTS)
__device__ __forceinline__ void cp16(uint32_t smem_dst, const void* gsrc) {
    asm volatile("cp.async.cg.shared.global [%0], [%1], 16;"
                 :: "r"(smem_dst), "l"(gsrc) : "memory");
}
__device__ __forceinline__ void cp_commit() {
    asm volatile("cp.async.commit_group;" ::: "memory");
}
template<int N>
__device__ __forceinline__ void cp_wait() {
    asm volatile("cp.async.wait_group %0;" :: "n"(N) : "memory");
}

// ---------------- device scratch (static, allowed) ----------------
__device__ float  g_part_s[512];
__device__ float  g_part_s2[512];
__device__ float  g_stats[2];
__device__ float  g_weffk[512*128];
__device__ float  g_weffv[512*128];
__device__ __nv_bfloat16 g_qh[BATCH*HEADS*HW*DK];   // pre-scaled Q, bf16, [bh][q][d]
__device__ __nv_bfloat16 g_kh[BATCH*HEADS*KHW*DK];  // K bf16 [bh][key][d]
__device__ __nv_bfloat16 g_vT[BATCH*HEADS*DK*KHW];  // V bf16 transposed [bh][d][key]
__device__ float  g_ctx[BATCH*HW*HD];

// ---------------- launch 0: per-block partial sums (deterministic) ----------------
__global__ void k_part(const float* __restrict__ x)
{
    float s = 0.f, s2 = 0.f;
    int base = blockIdx.x * (NTOT/512);
    for (int i = threadIdx.x; i < NTOT/512; i += 256) {
        float v = x[base + i];
        s  += v;
        s2  = fmaf(v, v, s2);
    }
    #pragma unroll
    for (int off = 16; off; off >>= 1) {
        s  += __shfl_down_sync(0xffffffffu, s,  off);
        s2 += __shfl_down_sync(0xffffffffu, s2, off);
    }
    __shared__ float sh[2][8];
    int lane = threadIdx.x & 31, w = threadIdx.x >> 5;
    if (lane == 0) { sh[0][w] = s; sh[1][w] = s2; }
    __syncthreads();
    if (threadIdx.x == 0) {
        float ts = 0.f, ts2 = 0.f;
        for (int i = 0; i < 8; i++) { ts += sh[0][i]; ts2 += sh[1][i]; }
        g_part_s[blockIdx.x]  = ts;
        g_part_s2[blockIdx.x] = ts2;
    }
}

// ---------------- launch 1: stats finalize (block 0) + weff fold (blocks 1..256) ----------------
__global__ void k_stats_weff(const float* __restrict__ fck_w, const float* __restrict__ wk,
                             const float* __restrict__ fcv_w, const float* __restrict__ wv)
{
    if (blockIdx.x == 0) {
        __shared__ double sh[512], sh2[512];
        int t = threadIdx.x;
        sh[t]  = (double)g_part_s[t];
        sh2[t] = (double)g_part_s2[t];
        __syncthreads();
        for (int o = 256; o; o >>= 1) {
            if (t < o) { sh[t] += sh[t+o]; sh2[t] += sh2[t+o]; }
            __syncthreads();
        }
        if (t == 0) {
            double n = (double)NTOT;
            double m = sh[0] / n;
            double var = sh2[0] / n - m*m;
            g_stats[0] = (float)m;
            g_stats[1] = (float)rsqrt(var + (double)EPS_LN);
        }
        return;
    }
    int b2 = blockIdx.x - 1;          // 0..255
    int f  = b2 & 127;
    const float* fw = (b2 >> 7) ? fcv_w : fck_w;
    const float* w8 = (b2 >> 7) ? wv    : wk;
    float*      out = (b2 >> 7) ? g_weffv : g_weffk;
    int idx = threadIdx.x;            // 0..511
    float acc = 0.f;
    #pragma unroll 16
    for (int co = 0; co < 64; co++)
        acc = fmaf(__ldg(&fw[f*64+co]), w8[co*512+idx], acc);
    out[idx*128+f] = acc;
}

// ---------------- launch 2: merged Q projection + PDC-conv K/V projection (bf16 out) ----------------
__global__ void __launch_bounds__(128) k_qkv(const float* __restrict__ x,
                    const float* __restrict__ fcq_w, const float* __restrict__ fcq_b,
                    const float* __restrict__ fck_b, const float* __restrict__ fcv_b)
{
    __shared__ float sm[9280];
    int b   = blockIdx.y;
    int tid = threadIdx.x;

    if (blockIdx.x < 256) {
        float* xs = sm;               // [c][pos], 64*16
        float* ws = sm + 1024;        // [c][f] padded 129
        int p0 = blockIdx.x * 16;
        float mean = g_stats[0], rstd = g_stats[1];

        for (int e = tid; e < 8192; e += 128) {
            int f = e >> 6, c = e & 63;
            ws[c*129+f] = fcq_w[e];
        }
        const float* xb = x + (size_t)b*C*HW;
        for (int e = tid; e < 1024; e += 128) {
            int c = e >> 4, pos = e & 15;
            xs[c*16+pos] = (xb[c*HW + p0 + pos] - mean) * rstd;
        }
        __syncthreads();

        int f = tid;
        float bias = fcq_b[f];
        ull acc2[8];
        #pragma unroll
        for (int i = 0; i < 8; i++) acc2[i] = pack2(bias, bias);
        for (int c = 0; c < 64; c++) {
            float w_ = ws[c*129+f];
            ull w2 = pack2(w_, w_);
            const ull* xr = (const ull*)(xs + c*16);
            #pragma unroll
            for (int i = 0; i < 8; i++) fma2(acc2[i], w2, xr[i], acc2[i]);
        }
        int h = f >> 5, d = f & 31;
        __nv_bfloat16* qb = g_qh + ((size_t)(b*HEADS+h)*HW + p0)*DK + d;
        #pragma unroll
        for (int i = 0; i < 8; i++) {
            float a0, a1; unpack2(a0, a1, acc2[i]);
            qb[(size_t)(2*i)*DK]   = __float2bfloat16(a0 * QK_SCALE);
            qb[(size_t)(2*i+1)*DK] = __float2bfloat16(a1 * QK_SCALE);
        }
    } else {
        float* gs = sm;               // [idx][pos] : 512*16
        int p0 = (blockIdx.x - 256) * 16;
        const float* xb = x + (size_t)b*C*HW;

        for (int e = tid; e < 8192; e += 128) {
            int idx = e >> 4;
            int pos = e & 15;
            int ci = idx >> 3, t = idx & 7;
            int pg = p0 + pos;
            int i = pg >> 5, j = pg & 31;
            int cy = i*2, cx = j*2;
            int k9 = (t < 4) ? t : t + 1;      // skip 3x3 center
            int ny = cy + (k9/3) - 1;
            int nx = cx + (k9%3) - 1;
            float ctr = xb[ci*HW + cy*WW + cx];
            float nb = 0.f;
            if (ny >= 0 && ny < HH && nx >= 0 && nx < WW)
                nb = xb[ci*HW + ny*WW + nx];
            gs[idx*16+pos] = nb - THETA*ctr;
        }
        __syncthreads();

        int f = tid;
        float bk = fck_b[f], bv = fcv_b[f];
        ull ak2[8], av2[8];
        #pragma unroll
        for (int i = 0; i < 8; i++) { ak2[i] = pack2(bk, bk); av2[i] = pack2(bv, bv); }
        #pragma unroll 4
        for (int idx = 0; idx < 512; idx++) {
            float wk_ = g_weffk[idx*128+f];
            float wv_ = g_weffv[idx*128+f];
            ull wk2 = pack2(wk_, wk_);
            ull wv2 = pack2(wv_, wv_);
            const ull* gr = (const ull*)(gs + idx*16);
            #pragma unroll
            for (int i = 0; i < 8; i++) {
                ull gg = gr[i];
                fma2(ak2[i], wk2, gg, ak2[i]);
                fma2(av2[i], wv2, gg, av2[i]);
            }
        }
        int h = f >> 5, d = f & 31;
        __nv_bfloat16* kb = g_kh + ((size_t)(b*HEADS+h)*KHW + p0)*DK + d;
        uint32_t* vb = (uint32_t*)(g_vT + ((size_t)(b*HEADS+h)*DK + d)*KHW + p0);
        #pragma unroll
        for (int i = 0; i < 8; i++) {
            float k0, k1, v0, v1;
            unpack2(k0, k1, ak2[i]);
            unpack2(v0, v1, av2[i]);
            kb[(size_t)(2*i)*DK]   = __float2bfloat16(k0);
            kb[(size_t)(2*i+1)*DK] = __float2bfloat16(k1);
            vb[i] = bf16x2_of(v0, v1);   // keys p0+2i, p0+2i+1 at dim d
        }
    }
}

// ---------------- launch 3: attention via mma.sync + cp.async double buffer ----------------
// CTA: 128 q-rows x one (b,h). 4 warps, warp w owns rows q0+32w..+31.
// 16 key tiles of 64; tile t+1 streams in via cp.async while tile t computes.
#define KT 64
__global__ void __launch_bounds__(128) k_attn(const float* __restrict__ Bmat)
{
    __shared__ __align__(16) __nv_bfloat16 Ksm[2][KT][40];     // keys x dims (pad 40)
    __shared__ __align__(16) __nv_bfloat16 Vsm[2][DK][KT+8];   // dims x keys (pad 72)
    int tid = threadIdx.x;
    int w = tid >> 5, l = tid & 31;
    int g = l >> 2, t = l & 3;
    int bh = blockIdx.y, h = bh & 3;
    int q0 = blockIdx.x * 128 + w * 32;

    const char* kgl = (const char*)(g_kh + (size_t)bh*KHW*DK);
    const char* vgl = (const char*)(g_vT + (size_t)bh*DK*KHW);

    // per-thread cp.async chunk coordinates (2 K chunks + 2 V chunks per tile)
    // K: 256 chunks of 16B; chunk c -> row r=c>>2, sub cc=c&3
    int kr0 = tid >> 2,          kc0 = tid & 3;
    int kr1 = (tid + 128) >> 2,  kc1 = (tid + 128) & 3;
    // V: 256 chunks; chunk c -> dim d=c>>3, sub cc=c&7
    int vd0 = tid >> 3,          vc0 = tid & 7;
    int vd1 = (tid + 128) >> 3,  vc1 = (tid + 128) & 7;

    uint32_t ks0[2], ks1[2], vs0[2], vs1[2];
    #pragma unroll
    for (int bf = 0; bf < 2; bf++) {
        ks0[bf] = (uint32_t)__cvta_generic_to_shared(&Ksm[bf][kr0][kc0*8]);
        ks1[bf] = (uint32_t)__cvta_generic_to_shared(&Ksm[bf][kr1][kc1*8]);
        vs0[bf] = (uint32_t)__cvta_generic_to_shared(&Vsm[bf][vd0][vc0*8]);
        vs1[bf] = (uint32_t)__cvta_generic_to_shared(&Vsm[bf][vd1][vc1*8]);
    }

    // Q a-frags (once): [mtile][kchunk][4]
    uint32_t qa[2][2][4];
    const __nv_bfloat16* Qb = g_qh + ((size_t)bh*HW + q0)*DK;
    #pragma unroll
    for (int mt = 0; mt < 2; mt++)
        #pragma unroll
        for (int kc = 0; kc < 2; kc++) {
            int r0 = mt*16 + g;
            qa[mt][kc][0] = *(const uint32_t*)(Qb + (size_t)r0*DK     + kc*16 + 2*t);
            qa[mt][kc][1] = *(const uint32_t*)(Qb + (size_t)(r0+8)*DK + kc*16 + 2*t);
            qa[mt][kc][2] = *(const uint32_t*)(Qb + (size_t)r0*DK     + kc*16 + 8 + 2*t);
            qa[mt][kc][3] = *(const uint32_t*)(Qb + (size_t)(r0+8)*DK + kc*16 + 8 + 2*t);
        }

    float o[2][4][4];                 // [mtile][dim-block][frag]
    float lsum[2][2];                 // [mtile][row g / g+8]
    #pragma unroll
    for (int mt = 0; mt < 2; mt++) {
        lsum[mt][0] = lsum[mt][1] = 0.f;
        #pragma unroll
        for (int db = 0; db < 4; db++)
            o[mt][db][0] = o[mt][db][1] = o[mt][db][2] = o[mt][db][3] = 0.f;
    }

    const float* Bb = Bmat + (size_t)h*HW*KHW;

    // preload tile 0 into buffer 0
    cp16(ks0[0], kgl + (size_t)(kr0)*64 + kc0*16);
    cp16(ks1[0], kgl + (size_t)(kr1)*64 + kc1*16);
    cp16(vs0[0], vgl + (size_t)vd0*(KHW*2) + vc0*16);
    cp16(vs1[0], vgl + (size_t)vd1*(KHW*2) + vc1*16);
    cp_commit();

    for (int tt = 0; tt < 16; tt++) {
        int c0 = tt * KT;
        int buf = tt & 1;
        // stream tile tt+1 into the other buffer
        if (tt < 15) {
            int c1 = c0 + KT;
            int nb_ = buf ^ 1;
            cp16(ks0[nb_], kgl + (size_t)(c1 + kr0)*64 + kc0*16);
            cp16(ks1[nb_], kgl + (size_t)(c1 + kr1)*64 + kc1*16);
            cp16(vs0[nb_], vgl + (size_t)vd0*(KHW*2) + c1*2 + vc0*16);
            cp16(vs1[nb_], vgl + (size_t)vd1*(KHW*2) + c1*2 + vc1*16);
            cp_commit();
            cp_wait<1>();          // tile tt resident
        } else {
            cp_wait<0>();
        }
        __syncthreads();

        #pragma unroll
        for (int half = 0; half < 2; half++) {
            int c32 = half * 32;
            // ---- S = Q K^T over 32 keys ----
            float s[2][4][4];
            #pragma unroll
            for (int mt = 0; mt < 2; mt++)
                #pragma unroll
                for (int nb = 0; nb < 4; nb++)
                    s[mt][nb][0] = s[mt][nb][1] = s[mt][nb][2] = s[mt][nb][3] = 0.f;
            #pragma unroll
            for (int nb = 0; nb < 4; nb++) {
                int key = c32 + 8*nb + g;
                uint32_t b0 = *(const uint32_t*)&Ksm[buf][key][2*t];
                uint32_t b1 = *(const uint32_t*)&Ksm[buf][key][8  + 2*t];
                uint32_t b2 = *(const uint32_t*)&Ksm[buf][key][16 + 2*t];
                uint32_t b3 = *(const uint32_t*)&Ksm[buf][key][24 + 2*t];
                #pragma unroll
                for (int mt = 0; mt < 2; mt++) {
                    mma_bf16(s[mt][nb], qa[mt][0], b0, b1);
                    mma_bf16(s[mt][nb], qa[mt][1], b2, b3);
                }
            }
            // ---- epilogue: +bias, exp, l, pack P (A-frags of next gemm) ----
            uint32_t pa[2][2][4];     // [mtile][kchunk16][4]
            #pragma unroll
            for (int mt = 0; mt < 2; mt++)
                #pragma unroll
                for (int nb = 0; nb < 4; nb++) {
                    int row = q0 + mt*16 + g;
                    size_t bidx = (size_t)row*KHW + c0 + c32 + 8*nb + 2*t;
                    float2 bv0 = *(const float2*)(Bb + bidx);
                    float2 bv1 = *(const float2*)(Bb + bidx + (size_t)8*KHW);
                    float p0 = __expf(s[mt][nb][0] + bv0.x);
                    float p1 = __expf(s[mt][nb][1] + bv0.y);
                    float p2 = __expf(s[mt][nb][2] + bv1.x);
                    float p3 = __expf(s[mt][nb][3] + bv1.y);
                    lsum[mt][0] += (p0 + p1);
                    lsum[mt][1] += (p2 + p3);
                    int u = nb >> 1, odd = nb & 1;
                    pa[mt][u][2*odd]     = bf16x2_of(p0, p1);
                    pa[mt][u][2*odd + 1] = bf16x2_of(p2, p3);
                }
            // ---- O += P V ----
            #pragma unroll
            for (int u = 0; u < 2; u++)
                #pragma unroll
                for (int db = 0; db < 4; db++) {
                    uint32_t b0 = *(const uint32_t*)&Vsm[buf][8*db + g][c32 + 16*u + 2*t];
                    uint32_t b1 = *(const uint32_t*)&Vsm[buf][8*db + g][c32 + 16*u + 8 + 2*t];
                    mma_bf16(o[0][db], pa[0][u], b0, b1);
                    mma_bf16(o[1][db], pa[1][u], b0, b1);
                }
        }
        __syncthreads();
    }

    // reduce l over the t-quad, normalize, store ctx
    #pragma unroll
    for (int mt = 0; mt < 2; mt++)
        #pragma unroll
        for (int r = 0; r < 2; r++) {
            float v = lsum[mt][r];
            v += __shfl_xor_sync(0xffffffffu, v, 1);
            v += __shfl_xor_sync(0xffffffffu, v, 2);
            lsum[mt][r] = 1.f / v;
        }
    int b = bh >> 2;
    #pragma unroll
    for (int mt = 0; mt < 2; mt++) {
        int row = q0 + mt*16 + g;
        #pragma unroll
        for (int db = 0; db < 4; db++) {
            int dim = h*DK + 8*db + 2*t;
            float2 lo = make_float2(o[mt][db][0]*lsum[mt][0], o[mt][db][1]*lsum[mt][0]);
            float2 hi = make_float2(o[mt][db][2]*lsum[mt][1], o[mt][db][3]*lsum[mt][1]);
            *(float2*)(g_ctx + ((size_t)b*HW + row)*HD + dim)     = lo;
            *(float2*)(g_ctx + ((size_t)b*HW + row + 8)*HD + dim) = hi;
        }
    }
}

// ---------------- launch 4: output projection + residual, f32x2 packed ----------------
__global__ void k_out(const float* __restrict__ x,
                      const float* __restrict__ fco_w,
                      const float* __restrict__ fco_b,
                      float* __restrict__ out)
{
    __shared__ float cs[16*128];
    __shared__ float ws2[64*130];
    int b   = blockIdx.y;
    int p0  = blockIdx.x * 16;
    int tid = threadIdx.x;

    for (int e = tid; e < 8192; e += 256) {
        int ch = e >> 7, k = e & 127;
        ws2[ch*130+k] = fco_w[e];
    }
    const float* ctx = g_ctx + ((size_t)b*HW + p0)*HD;
    for (int e = tid; e < 2048; e += 256) cs[e] = ctx[e];
    __syncthreads();

    int ch = tid & 63;
    int pg = tid >> 6;
    ull acc2[4];
    #pragma unroll
    for (int pi = 0; pi < 4; pi++) acc2[pi] = 0ull;
    const ull* wr = (const ull*)(ws2 + ch*130);
    #pragma unroll 4
    for (int kp = 0; kp < 64; kp++) {
        ull w2 = wr[kp];
        #pragma unroll
        for (int pi = 0; pi < 4; pi++) {
            ull c2 = *(const ull*)(cs + (pg*4+pi)*128 + 2*kp);
            fma2(acc2[pi], w2, c2, acc2[pi]);
        }
    }
    float bias = fco_b[ch];
    #pragma unroll
    for (int pi = 0; pi < 4; pi++) {
        float a0, a1; unpack2(a0, a1, acc2[pi]);
        int pos = pg*4 + pi;
        size_t oi = (size_t)b*(C*HW) + (size_t)(p0+pos)*64 + ch;
        out[oi] = (a0 + a1) + bias + x[oi];
    }
}

// ---------------- launcher (5 launches; k_attn is launch idx 3) ----------------
extern "C" void kernel_launch(void* const* d_in, const int* in_sizes, int n_in,
                              void* d_out, int out_size)
{
    (void)n_in; (void)out_size; (void)in_sizes;
    const float* x      = (const float*)d_in[0];
    const float* wk     = (const float*)d_in[1];
    const float* wv     = (const float*)d_in[2];
    const float* fcq_w  = (const float*)d_in[3];
    const float* fcq_b  = (const float*)d_in[4];
    const float* fck_w  = (const float*)d_in[5];
    const float* fck_b  = (const float*)d_in[6];
    const float* fcv_w  = (const float*)d_in[7];
    const float* fcv_b  = (const float*)d_in[8];
    const float* fco_w  = (const float*)d_in[9];
    const float* fco_b  = (const float*)d_in[10];
    const float* Bmat   = (const float*)d_in[11];
    float* out = (float*)d_out;

    k_part<<<512, 256>>>(x);
    k_stats_weff<<<257, 512>>>(fck_w, wk, fcv_w, wv);
    k_qkv<<<dim3(256+64, BATCH), 128>>>(x, fcq_w, fcq_b, fck_b, fcv_b);
    k_attn<<<dim3(HW/128, BATCH*HEADS), 128>>>(Bmat);
    k_out<<<dim3(HW/16, BATCH), 256>>>(x, fco_w, fco_b, out);
}

// round 10
// speedup vs baseline: 1.0881x; 1.0881x over previous
#include <cuda_runtime.h>
#include <cuda_bf16.h>
#include <math.h>
#include <stdint.h>

// ---------------- problem constants (fixed shapes) ----------------
#define BATCH 8
#define C     64
#define HH    64
#define WW    64
#define HW    4096          // 64*64
#define HEADS 4
#define DK    32
#define HD    128           // HEADS*DK
#define KHW   1024          // 32*32 (stride-2 output)
#define THETA 0.5f
#define EPS_LN 1e-5f
#define NTOT  (BATCH*C*HW)  // 2097152
#define QK_SCALE 0.17677669529663687f  // 1/sqrt(32)

typedef unsigned long long ull;

// packed fp32x2 helpers
__device__ __forceinline__ void fma2(ull& d, ull a, ull b, ull c) {
    asm("fma.rn.f32x2 %0, %1, %2, %3;" : "=l"(d) : "l"(a), "l"(b), "l"(c));
}
__device__ __forceinline__ ull pack2(float lo, float hi) {
    ull r; asm("mov.b64 %0, {%1, %2};" : "=l"(r) : "f"(lo), "f"(hi)); return r;
}
__device__ __forceinline__ void unpack2(float& lo, float& hi, ull v) {
    asm("mov.b64 {%0, %1}, %2;" : "=f"(lo), "=f"(hi) : "l"(v));
}
__device__ __forceinline__ uint32_t bf16x2_of(float a, float b) {
    uint32_t r;
    asm("cvt.rn.satfinite.bf16x2.f32 %0, %1, %2;" : "=r"(r) : "f"(b), "f"(a));
    return r;   // lo=a, hi=b
}

// warp mma: D(16x8,f32) += A(16x16,bf16,row) * B(16x8,bf16,col)
__device__ __forceinline__ void mma_bf16(float* d, const uint32_t* a,
                                         uint32_t b0, uint32_t b1) {
    asm volatile("mma.sync.aligned.m16n8k16.row.col.f32.bf16.bf16.f32 "
        "{%0,%1,%2,%3}, {%4,%5,%6,%7}, {%8,%9}, {%0,%1,%2,%3};"
        : "+f"(d[0]), "+f"(d[1]), "+f"(d[2]), "+f"(d[3])
        : "r"(a[0]), "r"(a[1]), "r"(a[2]), "r"(a[3]), "r"(b0), "r"(b1));
}

// ---------------- device scratch (static, allowed) ----------------
__device__ float  g_part_s[512];
__device__ float  g_part_s2[512];
__device__ float  g_stats[2];
__device__ float  g_weffk[512*128];
__device__ float  g_weffv[512*128];
__device__ __nv_bfloat16 g_qh[BATCH*HEADS*HW*DK];   // pre-scaled Q, bf16, [bh][q][d]
__device__ __nv_bfloat16 g_kh[BATCH*HEADS*KHW*DK];  // K bf16 [bh][key][d]
__device__ __nv_bfloat16 g_vT[BATCH*HEADS*DK*KHW];  // V bf16 transposed [bh][d][key]
__device__ float  g_ctx[BATCH*HW*HD];

// ---------------- launch 0: per-block partial sums (deterministic) ----------------
__global__ void k_part(const float* __restrict__ x)
{
    float s = 0.f, s2 = 0.f;
    int base = blockIdx.x * (NTOT/512);
    for (int i = threadIdx.x; i < NTOT/512; i += 256) {
        float v = x[base + i];
        s  += v;
        s2  = fmaf(v, v, s2);
    }
    #pragma unroll
    for (int off = 16; off; off >>= 1) {
        s  += __shfl_down_sync(0xffffffffu, s,  off);
        s2 += __shfl_down_sync(0xffffffffu, s2, off);
    }
    __shared__ float sh[2][8];
    int lane = threadIdx.x & 31, w = threadIdx.x >> 5;
    if (lane == 0) { sh[0][w] = s; sh[1][w] = s2; }
    __syncthreads();
    if (threadIdx.x == 0) {
        float ts = 0.f, ts2 = 0.f;
        for (int i = 0; i < 8; i++) { ts += sh[0][i]; ts2 += sh[1][i]; }
        g_part_s[blockIdx.x]  = ts;
        g_part_s2[blockIdx.x] = ts2;
    }
}

// ---------------- launch 1: stats finalize (block 0) + weff fold (blocks 1..256) ----------------
__global__ void k_stats_weff(const float* __restrict__ fck_w, const float* __restrict__ wk,
                             const float* __restrict__ fcv_w, const float* __restrict__ wv)
{
    if (blockIdx.x == 0) {
        __shared__ double sh[512], sh2[512];
        int t = threadIdx.x;
        sh[t]  = (double)g_part_s[t];
        sh2[t] = (double)g_part_s2[t];
        __syncthreads();
        for (int o = 256; o; o >>= 1) {
            if (t < o) { sh[t] += sh[t+o]; sh2[t] += sh2[t+o]; }
            __syncthreads();
        }
        if (t == 0) {
            double n = (double)NTOT;
            double m = sh[0] / n;
            double var = sh2[0] / n - m*m;
            g_stats[0] = (float)m;
            g_stats[1] = (float)rsqrt(var + (double)EPS_LN);
        }
        return;
    }
    int b2 = blockIdx.x - 1;          // 0..255
    int f  = b2 & 127;
    const float* fw = (b2 >> 7) ? fcv_w : fck_w;
    const float* w8 = (b2 >> 7) ? wv    : wk;
    float*      out = (b2 >> 7) ? g_weffv : g_weffk;
    int idx = threadIdx.x;            // 0..511
    float acc = 0.f;
    #pragma unroll 16
    for (int co = 0; co < 64; co++)
        acc = fmaf(__ldg(&fw[f*64+co]), w8[co*512+idx], acc);
    out[idx*128+f] = acc;
}

// ---------------- launch 2: merged Q projection + PDC-conv K/V projection (bf16 out) ----------------
__global__ void __launch_bounds__(128) k_qkv(const float* __restrict__ x,
                    const float* __restrict__ fcq_w, const float* __restrict__ fcq_b,
                    const float* __restrict__ fck_b, const float* __restrict__ fcv_b)
{
    __shared__ float sm[9280];
    int b   = blockIdx.y;
    int tid = threadIdx.x;

    if (blockIdx.x < 256) {
        float* xs = sm;               // [c][pos], 64*16
        float* ws = sm + 1024;        // [c][f] padded 129
        int p0 = blockIdx.x * 16;
        float mean = g_stats[0], rstd = g_stats[1];

        for (int e = tid; e < 8192; e += 128) {
            int f = e >> 6, c = e & 63;
            ws[c*129+f] = fcq_w[e];
        }
        const float* xb = x + (size_t)b*C*HW;
        for (int e = tid; e < 1024; e += 128) {
            int c = e >> 4, pos = e & 15;
            xs[c*16+pos] = (xb[c*HW + p0 + pos] - mean) * rstd;
        }
        __syncthreads();

        int f = tid;
        float bias = fcq_b[f];
        ull acc2[8];
        #pragma unroll
        for (int i = 0; i < 8; i++) acc2[i] = pack2(bias, bias);
        for (int c = 0; c < 64; c++) {
            float w_ = ws[c*129+f];
            ull w2 = pack2(w_, w_);
            const ull* xr = (const ull*)(xs + c*16);
            #pragma unroll
            for (int i = 0; i < 8; i++) fma2(acc2[i], w2, xr[i], acc2[i]);
        }
        int h = f >> 5, d = f & 31;
        __nv_bfloat16* qb = g_qh + ((size_t)(b*HEADS+h)*HW + p0)*DK + d;
        #pragma unroll
        for (int i = 0; i < 8; i++) {
            float a0, a1; unpack2(a0, a1, acc2[i]);
            qb[(size_t)(2*i)*DK]   = __float2bfloat16(a0 * QK_SCALE);
            qb[(size_t)(2*i+1)*DK] = __float2bfloat16(a1 * QK_SCALE);
        }
    } else {
        float* gs = sm;               // [idx][pos] : 512*16
        int p0 = (blockIdx.x - 256) * 16;
        const float* xb = x + (size_t)b*C*HW;

        for (int e = tid; e < 8192; e += 128) {
            int idx = e >> 4;
            int pos = e & 15;
            int ci = idx >> 3, t = idx & 7;
            int pg = p0 + pos;
            int i = pg >> 5, j = pg & 31;
            int cy = i*2, cx = j*2;
            int k9 = (t < 4) ? t : t + 1;      // skip 3x3 center
            int ny = cy + (k9/3) - 1;
            int nx = cx + (k9%3) - 1;
            float ctr = xb[ci*HW + cy*WW + cx];
            float nb = 0.f;
            if (ny >= 0 && ny < HH && nx >= 0 && nx < WW)
                nb = xb[ci*HW + ny*WW + nx];
            gs[idx*16+pos] = nb - THETA*ctr;
        }
        __syncthreads();

        int f = tid;
        float bk = fck_b[f], bv = fcv_b[f];
        ull ak2[8], av2[8];
        #pragma unroll
        for (int i = 0; i < 8; i++) { ak2[i] = pack2(bk, bk); av2[i] = pack2(bv, bv); }
        #pragma unroll 4
        for (int idx = 0; idx < 512; idx++) {
            float wk_ = g_weffk[idx*128+f];
            float wv_ = g_weffv[idx*128+f];
            ull wk2 = pack2(wk_, wk_);
            ull wv2 = pack2(wv_, wv_);
            const ull* gr = (const ull*)(gs + idx*16);
            #pragma unroll
            for (int i = 0; i < 8; i++) {
                ull gg = gr[i];
                fma2(ak2[i], wk2, gg, ak2[i]);
                fma2(av2[i], wv2, gg, av2[i]);
            }
        }
        int h = f >> 5, d = f & 31;
        __nv_bfloat16* kb = g_kh + ((size_t)(b*HEADS+h)*KHW + p0)*DK + d;
        uint32_t* vb = (uint32_t*)(g_vT + ((size_t)(b*HEADS+h)*DK + d)*KHW + p0);
        #pragma unroll
        for (int i = 0; i < 8; i++) {
            float k0, k1, v0, v1;
            unpack2(k0, k1, ak2[i]);
            unpack2(v0, v1, av2[i]);
            kb[(size_t)(2*i)*DK]   = __float2bfloat16(k0);
            kb[(size_t)(2*i+1)*DK] = __float2bfloat16(k1);
            vb[i] = bf16x2_of(v0, v1);   // keys p0+2i, p0+2i+1 at dim d
        }
    }
}

// ---------------- launch 3: attention via mma.sync (bf16 HMMA, fp32 accum) ----------------
// CTA: 64 q-rows x one (b,h). 4 warps, warp w owns rows q0..q0+15 (16 rows).
// Small per-warp state -> <=102 regs -> 5 CTAs/SM for latency hiding.
#define KT 64
__global__ void __launch_bounds__(128, 5) k_attn(const float* __restrict__ Bmat)
{
    __shared__ __align__(16) __nv_bfloat16 Ksm[KT][40];     // keys x dims (pad 40)
    __shared__ __align__(16) __nv_bfloat16 Vsm[DK][KT+8];   // dims x keys (pad 72)
    int tid = threadIdx.x;
    int w = tid >> 5, l = tid & 31;
    int g = l >> 2, t = l & 3;
    int bh = blockIdx.y, h = bh & 3;
    int q0 = blockIdx.x * 64 + w * 16;

    // Q a-frags (once): [kchunk][4] for this warp's 16 rows
    uint32_t qa[2][4];
    const __nv_bfloat16* Qb = g_qh + ((size_t)bh*HW + q0)*DK;
    #pragma unroll
    for (int kc = 0; kc < 2; kc++) {
        qa[kc][0] = *(const uint32_t*)(Qb + (size_t)g*DK     + kc*16 + 2*t);
        qa[kc][1] = *(const uint32_t*)(Qb + (size_t)(g+8)*DK + kc*16 + 2*t);
        qa[kc][2] = *(const uint32_t*)(Qb + (size_t)g*DK     + kc*16 + 8 + 2*t);
        qa[kc][3] = *(const uint32_t*)(Qb + (size_t)(g+8)*DK + kc*16 + 8 + 2*t);
    }

    float o[4][4];                    // [dim-block][frag]
    float lsum[2];                    // rows g / g+8
    lsum[0] = lsum[1] = 0.f;
    #pragma unroll
    for (int db = 0; db < 4; db++)
        o[db][0] = o[db][1] = o[db][2] = o[db][3] = 0.f;

    const float* Bb = Bmat + (size_t)h*HW*KHW;
    const uint32_t* kgl = (const uint32_t*)(g_kh + (size_t)bh*KHW*DK);
    const __nv_bfloat16* vgl = g_vT + (size_t)bh*DK*KHW;

    for (int c0 = 0; c0 < KHW; c0 += KT) {
        __syncthreads();
        // K tile: 64 keys x 16 u32 (row-major [key][dim]) = 1024 u32
        #pragma unroll
        for (int i = 0; i < 8; i++) {
            int e = tid + i*128;
            int r = e >> 4, c = e & 15;
            ((uint32_t*)&Ksm[r][0])[c] = kgl[(size_t)(c0 + r)*16 + c];
        }
        // V tile: 32 dims x 32 u32 (transposed [dim][key], 64 keys) = 1024 u32
        #pragma unroll
        for (int i = 0; i < 8; i++) {
            int e = tid + i*128;
            int d = e >> 5, c = e & 31;
            ((uint32_t*)&Vsm[d][0])[c] =
                ((const uint32_t*)(vgl + (size_t)d*KHW + c0))[c];
        }
        __syncthreads();

        #pragma unroll
        for (int half = 0; half < 2; half++) {
            int c32 = half * 32;
            // ---- S = Q K^T over 32 keys ----
            float s[4][4];
            #pragma unroll
            for (int nb = 0; nb < 4; nb++)
                s[nb][0] = s[nb][1] = s[nb][2] = s[nb][3] = 0.f;
            #pragma unroll
            for (int nb = 0; nb < 4; nb++) {
                int key = c32 + 8*nb + g;
                uint32_t b0 = *(const uint32_t*)&Ksm[key][2*t];
                uint32_t b1 = *(const uint32_t*)&Ksm[key][8  + 2*t];
                uint32_t b2 = *(const uint32_t*)&Ksm[key][16 + 2*t];
                uint32_t b3 = *(const uint32_t*)&Ksm[key][24 + 2*t];
                mma_bf16(s[nb], qa[0], b0, b1);
                mma_bf16(s[nb], qa[1], b2, b3);
            }
            // ---- epilogue: +bias, exp, l, pack P (A-frags of next gemm) ----
            uint32_t pa[2][4];        // [kchunk16][4]
            #pragma unroll
            for (int nb = 0; nb < 4; nb++) {
                int row = q0 + g;
                size_t bidx = (size_t)row*KHW + c0 + c32 + 8*nb + 2*t;
                float2 bv0 = *(const float2*)(Bb + bidx);
                float2 bv1 = *(const float2*)(Bb + bidx + (size_t)8*KHW);
                float p0 = __expf(s[nb][0] + bv0.x);
                float p1 = __expf(s[nb][1] + bv0.y);
                float p2 = __expf(s[nb][2] + bv1.x);
                float p3 = __expf(s[nb][3] + bv1.y);
                lsum[0] += (p0 + p1);
                lsum[1] += (p2 + p3);
                int u = nb >> 1, odd = nb & 1;
                pa[u][2*odd]     = bf16x2_of(p0, p1);
                pa[u][2*odd + 1] = bf16x2_of(p2, p3);
            }
            // ---- O += P V ----
            #pragma unroll
            for (int u = 0; u < 2; u++)
                #pragma unroll
                for (int db = 0; db < 4; db++) {
                    uint32_t b0 = *(const uint32_t*)&Vsm[8*db + g][c32 + 16*u + 2*t];
                    uint32_t b1 = *(const uint32_t*)&Vsm[8*db + g][c32 + 16*u + 8 + 2*t];
                    mma_bf16(o[db], pa[u], b0, b1);
                }
        }
    }

    // reduce l over the t-quad, normalize, store ctx
    #pragma unroll
    for (int r = 0; r < 2; r++) {
        float v = lsum[r];
        v += __shfl_xor_sync(0xffffffffu, v, 1);
        v += __shfl_xor_sync(0xffffffffu, v, 2);
        lsum[r] = 1.f / v;
    }
    int b = bh >> 2;
    int row = q0 + g;
    #pragma unroll
    for (int db = 0; db < 4; db++) {
        int dim = h*DK + 8*db + 2*t;
        float2 lo = make_float2(o[db][0]*lsum[0], o[db][1]*lsum[0]);
        float2 hi = make_float2(o[db][2]*lsum[1], o[db][3]*lsum[1]);
        *(float2*)(g_ctx + ((size_t)b*HW + row)*HD + dim)     = lo;
        *(float2*)(g_ctx + ((size_t)b*HW + row + 8)*HD + dim) = hi;
    }
}

// ---------------- launch 4: output projection + residual, f32x2 packed ----------------
__global__ void k_out(const float* __restrict__ x,
                      const float* __restrict__ fco_w,
                      const float* __restrict__ fco_b,
                      float* __restrict__ out)
{
    __shared__ float cs[16*128];
    __shared__ float ws2[64*130];
    int b   = blockIdx.y;
    int p0  = blockIdx.x * 16;
    int tid = threadIdx.x;

    for (int e = tid; e < 8192; e += 256) {
        int ch = e >> 7, k = e & 127;
        ws2[ch*130+k] = fco_w[e];
    }
    const float* ctx = g_ctx + ((size_t)b*HW + p0)*HD;
    for (int e = tid; e < 2048; e += 256) cs[e] = ctx[e];
    __syncthreads();

    int ch = tid & 63;
    int pg = tid >> 6;
    ull acc2[4];
    #pragma unroll
    for (int pi = 0; pi < 4; pi++) acc2[pi] = 0ull;
    const ull* wr = (const ull*)(ws2 + ch*130);
    #pragma unroll 4
    for (int kp = 0; kp < 64; kp++) {
        ull w2 = wr[kp];
        #pragma unroll
        for (int pi = 0; pi < 4; pi++) {
            ull c2 = *(const ull*)(cs + (pg*4+pi)*128 + 2*kp);
            fma2(acc2[pi], w2, c2, acc2[pi]);
        }
    }
    float bias = fco_b[ch];
    #pragma unroll
    for (int pi = 0; pi < 4; pi++) {
        float a0, a1; unpack2(a0, a1, acc2[pi]);
        int pos = pg*4 + pi;
        size_t oi = (size_t)b*(C*HW) + (size_t)(p0+pos)*64 + ch;
        out[oi] = (a0 + a1) + bias + x[oi];
    }
}

// ---------------- launcher (5 launches; k_attn is launch idx 3) ----------------
extern "C" void kernel_launch(void* const* d_in, const int* in_sizes, int n_in,
                              void* d_out, int out_size)
{
    (void)n_in; (void)out_size; (void)in_sizes;
    const float* x      = (const float*)d_in[0];
    const float* wk     = (const float*)d_in[1];
    const float* wv     = (const float*)d_in[2];
    const float* fcq_w  = (const float*)d_in[3];
    const float* fcq_b  = (const float*)d_in[4];
    const float* fck_w  = (const float*)d_in[5];
    const float* fck_b  = (const float*)d_in[6];
    const float* fcv_w  = (const float*)d_in[7];
    const float* fcv_b  = (const float*)d_in[8];
    const float* fco_w  = (const float*)d_in[9];
    const float* fco_b  = (const float*)d_in[10];
    const float* Bmat   = (const float*)d_in[11];
    float* out = (float*)d_out;

    k_part<<<512, 256>>>(x);
    k_stats_weff<<<257, 512>>>(fck_w, wk, fcv_w, wv);
    k_qkv<<<dim3(256+64, BATCH), 128>>>(x, fcq_w, fcq_b, fck_b, fcv_b);
    k_attn<<<dim3(HW/64, BATCH*HEADS), 128>>>(Bmat);
    k_out<<<dim3(HW/16, BATCH), 256>>>(x, fco_w, fco_b, out);
}